// round 14
// baseline (speedup 1.0000x reference)
#include <cuda_runtime.h>
#include <cuda_fp16.h>
#include <cuda_bf16.h>
#include <cuda_fp8.h>
#include <math.h>
#include <stdint.h>

// ---------------------------------------------------------------------------
// Problem constants (fixed by the reference)
// ---------------------------------------------------------------------------
#define NA        4096
#define ED        256      // EMBED_DIMS
#define NG        8        // NUM_GROUPS
#define GD        32       // GROUP_DIMS
#define NL        4        // NUM_LEVELS
#define NC        6        // NUM_CAMS
#define NPT       13       // NUM_PTS (7 fixed + 6 learnable)
#define NSAMP     312      // NC*NL*NPT
#define NSAMPP    313      // padded (bank destagger)
#define NWTS      2496     // NSAMP*NG
#define MAXCOR    1280     // >= NSAMP*4

// prologue role partition
#define NB_GEMM   1248     // (2496/64) * (4096/128)
#define NB_TRANS  22464    // 468 hw-tiles * 8 c-tiles * 6 cams
#define NB_SETUP  4096
#define NB_TOTAL  (NB_GEMM + NB_TRANS + NB_SETUP)

// level dims
__constant__ int   c_LW[4] = {176, 88, 44, 22};
__constant__ int   c_LH[4] = {64, 32, 16, 8};
__constant__ unsigned c_LB[4] = {0u, 17301504u, 21626880u, 22708224u};  // byte offsets (1B/elem)
__constant__ int   c_HW[4] = {11264, 2816, 704, 176};
__constant__ int   c_tileBase[5] = {0, 352, 440, 462, 468};  // cumulative 32-wide hw tiles

__constant__ float c_fix[21] = {
    0.f,0.f,0.f,  0.45f,0.f,0.f,  -0.45f,0.f,0.f,
    0.f,0.45f,0.f, 0.f,-0.45f,0.f, 0.f,0.f,0.45f, 0.f,0.f,-0.45f
};

// ---------------------------------------------------------------------------
// Scratch (static __device__ — device-code references ONLY; host-side address
// of a __device__ symbol is the host shadow and silently "works" via ATS).
// ---------------------------------------------------------------------------
__device__ __align__(16) unsigned char g_f8[22978560]; // 4 levels, NHWC, fp8 e4m3
__device__ float  g_logits[NA * NWTS];      // weight logits (softmaxed in agg)
__device__ float  g_p2d[NA * NPT * NC * 2]; // projected points
__device__ float  g_feats[NA * ED];         // aggregated features

// ---------------------------------------------------------------------------
// PROLOGUE mega-kernel: three independent roles in one launch.
//   blocks [0, NB_GEMM):               logits GEMM (tensor pipe)
//   blocks [NB_GEMM, +NB_TRANS):       CHW->HWC transpose + fp8 convert (HBM)
//   blocks [.., +NB_SETUP):            per-anchor keypoint setup (latency)
// Shared memory is a union (27.6 KB = GEMM role's requirement).
// ---------------------------------------------------------------------------
__global__ void __launch_bounds__(256) prologue_kernel(
    const float* __restrict__ f0, const float* __restrict__ f1,
    const float* __restrict__ f2, const float* __restrict__ f3,
    const float* __restrict__ inst, const float* __restrict__ anchor,
    const float* __restrict__ proj, const float* __restrict__ wh,
    const float* __restrict__ Wl, const float* __restrict__ bl,
    const float* __restrict__ Ww, const float* __restrict__ bw)
{
    __shared__ __align__(16) char sbuf[27648];
    int b = blockIdx.x;
    int tid = threadIdx.x;

    if (b < NB_GEMM) {
        // ------------------ role: logits GEMM (bf16 tensor cores) ------------
        float* C = g_logits;
        const float* A = inst;
        const float* Bm = Ww;
        const int N = NWTS, K = ED;
        __nv_bfloat16 (*As)[72]  = (__nv_bfloat16(*)[72])sbuf;           // 128x72
        __nv_bfloat16 (*Bst)[72] = (__nv_bfloat16(*)[72])(sbuf + 18432); // 64x72

        int lane = tid & 31, w = tid >> 5;
        int wm = w & 3, wn = w >> 2;
        int m0 = (b / 39) * 128, n0 = (b % 39) * 64;
        int g = lane >> 2, t = lane & 3;

        float d[2][4][4];
#pragma unroll
        for (int mt = 0; mt < 2; mt++)
#pragma unroll
            for (int nt = 0; nt < 4; nt++)
#pragma unroll
                for (int r = 0; r < 4; r++) d[mt][nt][r] = 0.f;

        for (int k0 = 0; k0 < K; k0 += 64) {
#pragma unroll
            for (int i = 0; i < 32; i++) {
                int e = i * 256 + tid;
                int row = e >> 6, kk = e & 63;
                As[row][kk] = __float2bfloat16(A[(size_t)(m0 + row) * K + k0 + kk]);
            }
#pragma unroll
            for (int i = 0; i < 16; i++) {
                int e = i * 256 + tid;
                int kk = e >> 6, n = e & 63;
                Bst[n][kk] = __float2bfloat16(Bm[(size_t)(k0 + kk) * N + n0 + n]);
            }
            __syncthreads();
#pragma unroll
            for (int ks = 0; ks < 4; ks++) {
                int kb = ks * 16;
                unsigned a[2][4], bb[4][2];
#pragma unroll
                for (int mt = 0; mt < 2; mt++) {
                    int rb = wm * 32 + mt * 16;
                    a[mt][0] = *(const unsigned*)&As[rb + g][kb + 2 * t];
                    a[mt][1] = *(const unsigned*)&As[rb + g + 8][kb + 2 * t];
                    a[mt][2] = *(const unsigned*)&As[rb + g][kb + 2 * t + 8];
                    a[mt][3] = *(const unsigned*)&As[rb + g + 8][kb + 2 * t + 8];
                }
#pragma unroll
                for (int nt = 0; nt < 4; nt++) {
                    int cb = wn * 32 + nt * 8;
                    bb[nt][0] = *(const unsigned*)&Bst[cb + g][kb + 2 * t];
                    bb[nt][1] = *(const unsigned*)&Bst[cb + g][kb + 2 * t + 8];
                }
#pragma unroll
                for (int mt = 0; mt < 2; mt++)
#pragma unroll
                    for (int nt = 0; nt < 4; nt++)
                        asm volatile(
                            "mma.sync.aligned.m16n8k16.row.col.f32.bf16.bf16.f32 "
                            "{%0,%1,%2,%3}, {%4,%5,%6,%7}, {%8,%9}, {%0,%1,%2,%3};"
                            : "+f"(d[mt][nt][0]), "+f"(d[mt][nt][1]),
                              "+f"(d[mt][nt][2]), "+f"(d[mt][nt][3])
                            : "r"(a[mt][0]), "r"(a[mt][1]), "r"(a[mt][2]), "r"(a[mt][3]),
                              "r"(bb[nt][0]), "r"(bb[nt][1]));
            }
            __syncthreads();
        }
#pragma unroll
        for (int mt = 0; mt < 2; mt++) {
            int rb = m0 + wm * 32 + mt * 16;
#pragma unroll
            for (int nt = 0; nt < 4; nt++) {
                int n = n0 + wn * 32 + nt * 8 + 2 * t;
                float b0 = bw[n], b1 = bw[n + 1];
                C[(size_t)(rb + g) * N + n]         = d[mt][nt][0] + b0;
                C[(size_t)(rb + g) * N + n + 1]     = d[mt][nt][1] + b1;
                C[(size_t)(rb + g + 8) * N + n]     = d[mt][nt][2] + b0;
                C[(size_t)(rb + g + 8) * N + n + 1] = d[mt][nt][3] + b1;
            }
        }
    } else if (b < NB_GEMM + NB_TRANS) {
        // ------------------ role: transpose + fp8 convert ---------------------
        float (*tile)[33] = (float(*)[33])sbuf;   // 32x33 floats = 4224 B
        int t = b - NB_GEMM;
        int bx  = t % 468;
        int r   = t / 468;
        int cy  = r % 8;          // channel tile
        int cam = r / 8;          // 0..5
        int lvl = 0;
#pragma unroll
        for (int l = 1; l < 4; l++) if (bx >= c_tileBase[l]) lvl = l;
        const float* src = (lvl == 0) ? f0 : (lvl == 1) ? f1 : (lvl == 2) ? f2 : f3;
        int HW = c_HW[lvl];
        unsigned dst_base = c_LB[lvl];

        int hw0 = (bx - c_tileBase[lvl]) * 32;
        int c0  = cy * 32;
        const float* s = src + (size_t)cam * ED * HW;
        unsigned char* d = g_f8 + dst_base + (size_t)cam * HW * ED;
        int tx = tid & 31, ty = tid >> 5;
#pragma unroll
        for (int i = 0; i < 32; i += 8) {
            int c  = c0 + ty + i;
            int hw = hw0 + tx;
            float v = (hw < HW) ? s[(size_t)c * HW + hw] : 0.f;
            tile[ty + i][tx] = v;
        }
        __syncthreads();
#pragma unroll
        for (int i = 0; i < 32; i += 8) {
            int hw = hw0 + ty + i;
            int c  = c0 + tx;
            if (hw < HW)
                d[(size_t)hw * ED + c] =
                    (unsigned char)__nv_cvt_float_to_fp8(tile[tx][ty + i], __NV_SATFINITE, __NV_E4M3);
        }
    } else {
        // ------------------ role: per-anchor setup ---------------------------
        float* sif    = (float*)sbuf;            // [256]
        float* sscale = sif + 256;               // [39]
        float* skp    = sscale + 40;             // [39]
        float* sR     = skp + 40;                // [9]
        float* sts    = sR + 9;                  // [6]
        int a = b - NB_GEMM - NB_TRANS;

        sif[tid] = inst[(size_t)a * ED + tid];
        if (tid < 21) sscale[tid] = c_fix[tid];
        __syncthreads();

        const float* an = anchor + (size_t)a * 11;

        if (tid < 18) {
            float acc = bl[tid];
#pragma unroll 8
            for (int i = 0; i < ED; i++) acc = fmaf(sif[i], Wl[i * 18 + tid], acc);
            acc = fminf(fmaxf(acc, -9.21f), 9.21f);
            float sg = 1.f / (1.f + expf(-acc));
            sscale[21 + tid] = sg - 0.5f;
        }
        if (tid == 32) {
            float t0 = an[0], t1 = an[1], t2 = an[2];
            float s0 = an[3], s1 = an[4], s2 = an[5];
            float qw = an[6], qx = an[7], qy = an[8], qz = an[9];
            float inv = rsqrtf(qw*qw + qx*qx + qy*qy + qz*qz);
            qw *= inv; qx *= inv; qy *= inv; qz *= inv;
            float R00 = 1.f - 2.f*(qy*qy + qz*qz), R01 = 2.f*(qx*qy - qw*qz), R02 = 2.f*(qx*qz + qw*qy);
            float R10 = 2.f*(qx*qy + qw*qz), R11 = 1.f - 2.f*(qx*qx + qz*qz), R12 = 2.f*(qy*qz - qw*qx);
            float R20 = 2.f*(qx*qz - qw*qy), R21 = 2.f*(qy*qz + qw*qx), R22 = 1.f - 2.f*(qx*qx + qy*qy);
            sR[0] = R00; sR[1] = R10; sR[2] = R20;
            sR[3] = R01; sR[4] = R11; sR[5] = R21;
            sR[6] = R02; sR[7] = R12; sR[8] = R22;
            sts[0] = t0; sts[1] = t1; sts[2] = t2;
            sts[3] = s0; sts[4] = s1; sts[5] = s2;
        }
        __syncthreads();
        if (tid < NPT) {
            float v0 = sscale[tid*3+0] * sts[3];
            float v1 = sscale[tid*3+1] * sts[4];
            float v2 = sscale[tid*3+2] * sts[5];
            skp[tid*3+0] = sR[0]*v0 + sR[1]*v1 + sR[2]*v2 + sts[0];
            skp[tid*3+1] = sR[3]*v0 + sR[4]*v1 + sR[5]*v2 + sts[1];
            skp[tid*3+2] = sR[6]*v0 + sR[7]*v1 + sR[8]*v2 + sts[2];
        }
        __syncthreads();
        if (tid < NPT * NC) {
            int pt = tid / NC, cam = tid % NC;
            float x = skp[pt*3+0], y = skp[pt*3+1], z = skp[pt*3+2];
            const float* P = proj + cam * 16;
            float px = P[0]*x + P[1]*y + P[2]*z  + P[3];
            float py = P[4]*x + P[5]*y + P[6]*z  + P[7];
            float pz = P[8]*x + P[9]*y + P[10]*z + P[11];
            pz = fmaxf(pz, 1e-5f);
            float u = (px / pz) / wh[cam*2+0];
            float v = (py / pz) / wh[cam*2+1];
            u = fminf(fmaxf(u, 0.f), 0.9999f);
            v = fminf(fmaxf(v, 0.f), 0.9999f);
            g_p2d[((size_t)a * (NPT*NC) + tid) * 2 + 0] = u;
            g_p2d[((size_t)a * (NPT*NC) + tid) * 2 + 1] = v;
        }
    }
}

// ---------------------------------------------------------------------------
// Out GEMM (bf16 tensor cores): d_out = g_feats @ Wo + bo + inst
// ---------------------------------------------------------------------------
__global__ void __launch_bounds__(256) gemm_bf16_out(
    const float* __restrict__ Bm, const float* __restrict__ bias,
    const float* __restrict__ res, float* __restrict__ C)
{
    const float* A = g_feats;
    const int N = ED, K = ED;
    __shared__ __nv_bfloat16 As[128][72];
    __shared__ __nv_bfloat16 Bst[64][72];

    int tid = threadIdx.x;
    int lane = tid & 31, w = tid >> 5;
    int wm = w & 3, wn = w >> 2;
    int m0 = blockIdx.y * 128, n0 = blockIdx.x * 64;
    int g = lane >> 2, t = lane & 3;

    float d[2][4][4];
#pragma unroll
    for (int mt = 0; mt < 2; mt++)
#pragma unroll
        for (int nt = 0; nt < 4; nt++)
#pragma unroll
            for (int r = 0; r < 4; r++) d[mt][nt][r] = 0.f;

    for (int k0 = 0; k0 < K; k0 += 64) {
#pragma unroll
        for (int i = 0; i < 32; i++) {
            int e = i * 256 + tid;
            int row = e >> 6, kk = e & 63;
            As[row][kk] = __float2bfloat16(A[(size_t)(m0 + row) * K + k0 + kk]);
        }
#pragma unroll
        for (int i = 0; i < 16; i++) {
            int e = i * 256 + tid;
            int kk = e >> 6, n = e & 63;
            Bst[n][kk] = __float2bfloat16(Bm[(size_t)(k0 + kk) * N + n0 + n]);
        }
        __syncthreads();
#pragma unroll
        for (int ks = 0; ks < 4; ks++) {
            int kb = ks * 16;
            unsigned a[2][4], b[4][2];
#pragma unroll
            for (int mt = 0; mt < 2; mt++) {
                int rb = wm * 32 + mt * 16;
                a[mt][0] = *(const unsigned*)&As[rb + g][kb + 2 * t];
                a[mt][1] = *(const unsigned*)&As[rb + g + 8][kb + 2 * t];
                a[mt][2] = *(const unsigned*)&As[rb + g][kb + 2 * t + 8];
                a[mt][3] = *(const unsigned*)&As[rb + g + 8][kb + 2 * t + 8];
            }
#pragma unroll
            for (int nt = 0; nt < 4; nt++) {
                int cb = wn * 32 + nt * 8;
                b[nt][0] = *(const unsigned*)&Bst[cb + g][kb + 2 * t];
                b[nt][1] = *(const unsigned*)&Bst[cb + g][kb + 2 * t + 8];
            }
#pragma unroll
            for (int mt = 0; mt < 2; mt++)
#pragma unroll
                for (int nt = 0; nt < 4; nt++)
                    asm volatile(
                        "mma.sync.aligned.m16n8k16.row.col.f32.bf16.bf16.f32 "
                        "{%0,%1,%2,%3}, {%4,%5,%6,%7}, {%8,%9}, {%0,%1,%2,%3};"
                        : "+f"(d[mt][nt][0]), "+f"(d[mt][nt][1]),
                          "+f"(d[mt][nt][2]), "+f"(d[mt][nt][3])
                        : "r"(a[mt][0]), "r"(a[mt][1]), "r"(a[mt][2]), "r"(a[mt][3]),
                          "r"(b[nt][0]), "r"(b[nt][1]));
        }
        __syncthreads();
    }
#pragma unroll
    for (int mt = 0; mt < 2; mt++) {
        int rb = m0 + wm * 32 + mt * 16;
#pragma unroll
        for (int nt = 0; nt < 4; nt++) {
            int n = n0 + wn * 32 + nt * 8 + 2 * t;
            float b0 = bias[n], b1 = bias[n + 1];
            float v00 = d[mt][nt][0] + b0 + res[(size_t)(rb + g) * N + n];
            float v01 = d[mt][nt][1] + b1 + res[(size_t)(rb + g) * N + n + 1];
            float v10 = d[mt][nt][2] + b0 + res[(size_t)(rb + g + 8) * N + n];
            float v11 = d[mt][nt][3] + b1 + res[(size_t)(rb + g + 8) * N + n + 1];
            C[(size_t)(rb + g) * N + n]         = v00;
            C[(size_t)(rb + g) * N + n + 1]     = v01;
            C[(size_t)(rb + g + 8) * N + n]     = v10;
            C[(size_t)(rb + g + 8) * N + n + 1] = v11;
        }
    }
}

// ---------------------------------------------------------------------------
// per-sample bilinear corner metadata (shared by count & fill passes)
// ---------------------------------------------------------------------------
struct Corners {
    unsigned o[4];   // uint2-unit offsets (8 fp8 bytes per unit)
    float    w[4];   // bilinear weights (0 if invalid)
};

__device__ __forceinline__ Corners corner_meta(float2 p, int s) {
    int cam = s / (NL * NPT);
    int rr  = s % (NL * NPT);
    int lvl = rr / NPT;
    Corners r;
    int W = c_LW[lvl], H = c_LH[lvl];
    float x = p.x * (float)W - 0.5f;
    float y = p.y * (float)H - 0.5f;
    float xf = floorf(x), yf = floorf(y);
    float wx = x - xf, wy = y - yf;
    int x0 = (int)xf, y0 = (int)yf;
    int x1 = x0 + 1, y1 = y0 + 1;
    bool vx0 = (x0 >= 0) & (x0 < W);
    bool vx1 = (x1 >= 0) & (x1 < W);
    bool vy0 = (y0 >= 0) & (y0 < H);
    bool vy1 = (y1 >= 0) & (y1 < H);
    r.w[0] = (vx0 && vy0) ? (1.f - wx) * (1.f - wy) : 0.f;
    r.w[1] = (vx1 && vy0) ? wx * (1.f - wy) : 0.f;
    r.w[2] = (vx0 && vy1) ? (1.f - wx) * wy : 0.f;
    r.w[3] = (vx1 && vy1) ? wx * wy : 0.f;
    int x0c = min(max(x0, 0), W - 1), x1c = min(max(x1, 0), W - 1);
    int y0c = min(max(y0, 0), H - 1), y1c = min(max(y1, 0), H - 1);
    unsigned lb = c_LB[lvl];
    unsigned rowb = (unsigned)(cam * H);
    r.o[0] = (lb + ((rowb + (unsigned)y0c) * (unsigned)W + (unsigned)x0c) * 256u) >> 3;
    r.o[1] = (lb + ((rowb + (unsigned)y0c) * (unsigned)W + (unsigned)x1c) * 256u) >> 3;
    r.o[2] = (lb + ((rowb + (unsigned)y1c) * (unsigned)W + (unsigned)x0c) * 256u) >> 3;
    r.o[3] = (lb + ((rowb + (unsigned)y1c) * (unsigned)W + (unsigned)x1c) * 256u) >> 3;
    return r;
}

// ---------------------------------------------------------------------------
// Fused softmax + compacted bilinear aggregation (fp8, half2 MAC).
// R11/R13-proven version, byte-identical.
// ---------------------------------------------------------------------------
__global__ void __launch_bounds__(256) agg_kernel() {
    int a = blockIdx.x;
    int tid = threadIdx.x;
    int lane = tid & 31, warp = tid >> 5;

    __shared__ float  sw[NG * NSAMPP];            // softmaxed weights, [g][s]
    __shared__ float2 sp2[NPT * NC];
    __shared__ __align__(8) uint2 flist[MAXCOR];  // (off8, s<<16 | w_half)
    __shared__ int scnt[320];
    __shared__ int sbase[NSAMP];
    __shared__ int sT;
    __shared__ __align__(16) float spart[8 * ED];

    const float* lrow = g_logits + (size_t)a * NWTS;
    for (int i = tid; i < NWTS; i += 256) {
        int s = i >> 3, g = i & 7;
        sw[g * NSAMPP + s] = lrow[i];
    }
    if (tid < NPT * NC) sp2[tid] = ((const float2*)g_p2d)[(size_t)a * (NPT*NC) + tid];
    if (tid >= NSAMP && tid < 320) scnt[tid] = 0;
    __syncthreads();

    // per-group softmax over 312 entries (warp g handles group g; conflict-free)
    {
        float* swg = sw + warp * NSAMPP;
        float m = -1e30f;
        for (int i = lane; i < NSAMP; i += 32) m = fmaxf(m, swg[i]);
#pragma unroll
        for (int o = 16; o > 0; o >>= 1) m = fmaxf(m, __shfl_xor_sync(0xffffffffu, m, o));
        float ssum = 0.f;
        for (int i = lane; i < NSAMP; i += 32) {
            float e = __expf(swg[i] - m);
            swg[i] = e;
            ssum += e;
        }
#pragma unroll
        for (int o = 16; o > 0; o >>= 1) ssum += __shfl_xor_sync(0xffffffffu, ssum, o);
        float inv = 1.f / ssum;
        for (int i = lane; i < NSAMP; i += 32) swg[i] *= inv;
    }

    // pass 1: per-sample valid-corner counts
    for (int s = tid; s < NSAMP; s += 256) {
        int pt = (s % (NL * NPT)) % NPT, cam = s / (NL * NPT);
        Corners cr = corner_meta(sp2[pt * NC + cam], s);
        scnt[s] = (cr.w[0] != 0.f) + (cr.w[1] != 0.f) + (cr.w[2] != 0.f) + (cr.w[3] != 0.f);
    }
    __syncthreads();

    // deterministic exclusive scan over 312 counts
    if (tid < 32) {
        int l = tid;
        int tot = 0;
#pragma unroll
        for (int k = 0; k < 10; k++) {
            int s = l * 10 + k;
            tot += (s < NSAMP) ? scnt[s] : 0;
        }
        int inc = tot;
#pragma unroll
        for (int o = 1; o < 32; o <<= 1) {
            int v = __shfl_up_sync(0xffffffffu, inc, o);
            if (l >= o) inc += v;
        }
        int run = inc - tot;
#pragma unroll
        for (int k = 0; k < 10; k++) {
            int s = l * 10 + k;
            if (s < NSAMP) { sbase[s] = run; run += scnt[s]; }
        }
        if (l == 31) sT = run;
    }
    __syncthreads();

    // pass 2: fill compacted corner list (weight stored as half)
    for (int s = tid; s < NSAMP; s += 256) {
        int pt = (s % (NL * NPT)) % NPT, cam = s / (NL * NPT);
        Corners cr = corner_meta(sp2[pt * NC + cam], s);
        int b = sbase[s];
        unsigned shi = ((unsigned)s) << 16;
#pragma unroll
        for (int k = 0; k < 4; k++) {
            if (cr.w[k] != 0.f) {
                unsigned wbits = (unsigned)__half_as_ushort(__float2half_rn(cr.w[k]));
                flist[b] = make_uint2(cr.o[k], shi | wbits);
                b++;
            }
        }
    }
    __syncthreads();

    const int T = sT;
    int g = lane >> 2;                    // group of this 8-channel slab
    const float* swg = sw + g * NSAMPP;
    __half2 hz = __float2half2_rn(0.f);
    __half2 h0 = hz, h1 = hz, h2a = hz, h3 = hz;
    const uint2* __restrict__ F8 = (const uint2*)g_f8;
#pragma unroll 4
    for (int j = warp; j < T; j += 8) {
        uint2 e = flist[j];                                   // broadcast LDS.64
        float w = swg[e.y >> 16] *
                  __half2float(__ushort_as_half((unsigned short)(e.y & 0xffffu)));
        __half2 wh = __float2half2_rn(w);
        uint2 u = __ldg(F8 + e.x + lane);
        __half2_raw r0 = __nv_cvt_fp8x2_to_halfraw2((__nv_fp8x2_storage_t)(u.x & 0xffffu), __NV_E4M3);
        __half2_raw r1 = __nv_cvt_fp8x2_to_halfraw2((__nv_fp8x2_storage_t)(u.x >> 16), __NV_E4M3);
        __half2_raw r2 = __nv_cvt_fp8x2_to_halfraw2((__nv_fp8x2_storage_t)(u.y & 0xffffu), __NV_E4M3);
        __half2_raw r3 = __nv_cvt_fp8x2_to_halfraw2((__nv_fp8x2_storage_t)(u.y >> 16), __NV_E4M3);
        h0  = __hfma2(wh, *reinterpret_cast<__half2*>(&r0), h0);
        h1  = __hfma2(wh, *reinterpret_cast<__half2*>(&r1), h1);
        h2a = __hfma2(wh, *reinterpret_cast<__half2*>(&r2), h2a);
        h3  = __hfma2(wh, *reinterpret_cast<__half2*>(&r3), h3);
    }
    {
        float2 f0 = __half22float2(h0), f1 = __half22float2(h1);
        float2 f2 = __half22float2(h2a), f3 = __half22float2(h3);
        float4* sp4 = (float4*)&spart[warp * ED + lane * 8];
        sp4[0] = make_float4(f0.x, f0.y, f1.x, f1.y);
        sp4[1] = make_float4(f2.x, f2.y, f3.x, f3.y);
    }
    __syncthreads();
    {
        int ch = tid;
        float r = spart[ch];
#pragma unroll
        for (int p = 1; p < 8; p++) r += spart[p * ED + ch];
        g_feats[(size_t)a * ED + ch] = r;
    }
}

// ---------------------------------------------------------------------------
// launch — inputs bound by unique element counts (order-proof); single stream
// ---------------------------------------------------------------------------
extern "C" void kernel_launch(void* const* d_in, const int* in_sizes, int n_in,
                              void* d_out, int out_size) {
    const float* inst = 0; const float* anchor = 0;
    const float* feat[4] = {0,0,0,0};
    const float* proj = 0; const float* wh = 0;
    const float* Wl = 0; const float* bl = 0;
    const float* Ww = 0; const float* bw = 0;
    const float* Wo = 0; const float* bo = 0;

    for (int i = 0; i < n_in; i++) {
        const float* p = (const float*)d_in[i];
        switch (in_sizes[i]) {
            case 1048576:  inst    = p; break;
            case 45056:    anchor  = p; break;
            case 17301504: feat[0] = p; break;
            case 4325376:  feat[1] = p; break;
            case 1081344:  feat[2] = p; break;
            case 270336:   feat[3] = p; break;
            case 96:       proj    = p; break;
            case 12:       wh      = p; break;
            case 4608:     Wl      = p; break;
            case 18:       bl      = p; break;
            case 638976:   Ww      = p; break;
            case 2496:     bw      = p; break;
            case 65536:    Wo      = p; break;
            case 256:      bo      = p; break;
            default: break;
        }
    }
    float* out = (float*)d_out;

    // 1) fused prologue: logits GEMM + transposes + setup, one launch
    prologue_kernel<<<NB_TOTAL, 256>>>(feat[0], feat[1], feat[2], feat[3],
                                       inst, anchor, proj, wh, Wl, bl, Ww, bw);

    // 2) fused softmax + compacted aggregation (fp8 features)
    agg_kernel<<<NA, 256>>>();

    // 3) output GEMM on tensor cores: g_feats @ Wo + bo + inst -> d_out
    {
        dim3 grid(ED / 64, NA / 128);
        gemm_bf16_out<<<grid, 256>>>(Wo, bo, inst, out);
    }
}

// round 15
// speedup vs baseline: 2.0673x; 2.0673x over previous
#include <cuda_runtime.h>
#include <cuda_fp16.h>
#include <cuda_bf16.h>
#include <math.h>
#include <stdint.h>

// ---------------------------------------------------------------------------
// Problem constants (fixed by the reference)
// ---------------------------------------------------------------------------
#define NA        4096
#define ED        256      // EMBED_DIMS
#define NG        8        // NUM_GROUPS
#define GD        32       // GROUP_DIMS
#define NL        4        // NUM_LEVELS
#define NC        6        // NUM_CAMS
#define NPT       13       // NUM_PTS (7 fixed + 6 learnable)
#define NSAMP     312      // NC*NL*NPT
#define NSAMPP    313      // padded (bank destagger)
#define NWTS      2496     // NSAMP*NG
#define MAXCOR    1280     // >= NSAMP*4

// level dims
__constant__ int   c_LW[4] = {176, 88, 44, 22};
__constant__ int   c_LH[4] = {64, 32, 16, 8};
__constant__ unsigned c_LB[4] = {0u, 17301504u, 21626880u, 22708224u};  // element offsets
__constant__ int   c_HW[4] = {11264, 2816, 704, 176};
__constant__ int   c_tileBase[5] = {0, 352, 440, 462, 468};  // cumulative 32-wide hw tiles

__constant__ float c_fix[21] = {
    0.f,0.f,0.f,  0.45f,0.f,0.f,  -0.45f,0.f,0.f,
    0.f,0.45f,0.f, 0.f,-0.45f,0.f, 0.f,0.f,0.45f, 0.f,0.f,-0.45f
};

// ---------------------------------------------------------------------------
// Scratch (static __device__ — device-code references ONLY; host-side address
// of a __device__ symbol is the host shadow and silently "works" via ATS).
// g_f16 MUST be 16B-aligned: accessed through uint4* (16B vector loads).
// ---------------------------------------------------------------------------
__device__ __align__(16) __half g_f16[22978560]; // 4 levels, NHWC, fp16
__device__ float  g_logits[NA * NWTS];      // weight logits (softmaxed in agg)
__device__ float  g_p2d[NA * NPT * NC * 2]; // projected points
__device__ float  g_feats[NA * ED];         // aggregated features

// ---------------------------------------------------------------------------
// 1) Fused CHW -> HWC transpose + fp32->fp16 convert, ALL levels, 1 launch.
// ---------------------------------------------------------------------------
__global__ void transpose_all(const float* __restrict__ f0, const float* __restrict__ f1,
                              const float* __restrict__ f2, const float* __restrict__ f3) {
    __shared__ float tile[32][33];
    int bx = blockIdx.x;
    int lvl = 0;
#pragma unroll
    for (int l = 1; l < 4; l++) if (bx >= c_tileBase[l]) lvl = l;
    const float* src = (lvl == 0) ? f0 : (lvl == 1) ? f1 : (lvl == 2) ? f2 : f3;
    int HW = c_HW[lvl];
    unsigned dst_base = c_LB[lvl];

    int cam = blockIdx.z;
    int hw0 = (bx - c_tileBase[lvl]) * 32;
    int c0  = blockIdx.y * 32;
    const float* s = src + (size_t)cam * ED * HW;
    __half* d = g_f16 + dst_base + (size_t)cam * HW * ED;
    int tx = threadIdx.x, ty = threadIdx.y;
#pragma unroll
    for (int i = 0; i < 32; i += 8) {
        int c  = c0 + ty + i;
        int hw = hw0 + tx;
        float v = (hw < HW) ? s[(size_t)c * HW + hw] : 0.f;
        tile[ty + i][tx] = v;
    }
    __syncthreads();
#pragma unroll
    for (int i = 0; i < 32; i += 8) {
        int hw = hw0 + ty + i;
        int c  = c0 + tx;
        if (hw < HW) d[(size_t)hw * ED + c] = __float2half(tile[tx][ty + i]);
    }
}

// ---------------------------------------------------------------------------
// 2) Per-anchor setup: learnable points, rotation, projection -> g_p2d
// ---------------------------------------------------------------------------
__global__ void __launch_bounds__(128) setup_kernel(
    const float* __restrict__ inst, const float* __restrict__ anchor,
    const float* __restrict__ proj, const float* __restrict__ wh,
    const float* __restrict__ Wl, const float* __restrict__ bl)
{
    int a = blockIdx.x;
    int tid = threadIdx.x;
    __shared__ float sif[ED];
    __shared__ float sscale[NPT * 3];
    __shared__ float skp[NPT * 3];
    __shared__ float sR[9];
    __shared__ float sts[6];

    const float* f = inst + (size_t)a * ED;
    sif[tid]       = f[tid];
    sif[tid + 128] = f[tid + 128];
    if (tid < 21) sscale[tid] = c_fix[tid];
    __syncthreads();

    const float* an = anchor + (size_t)a * 11;

    if (tid < 18) {
        float acc = bl[tid];
#pragma unroll 8
        for (int i = 0; i < ED; i++) acc = fmaf(sif[i], Wl[i * 18 + tid], acc);
        acc = fminf(fmaxf(acc, -9.21f), 9.21f);
        float sg = 1.f / (1.f + expf(-acc));
        sscale[21 + tid] = sg - 0.5f;
    }
    if (tid == 32) {
        float t0 = an[0], t1 = an[1], t2 = an[2];
        float s0 = an[3], s1 = an[4], s2 = an[5];
        float qw = an[6], qx = an[7], qy = an[8], qz = an[9];
        float inv = rsqrtf(qw*qw + qx*qx + qy*qy + qz*qz);
        qw *= inv; qx *= inv; qy *= inv; qz *= inv;
        float R00 = 1.f - 2.f*(qy*qy + qz*qz), R01 = 2.f*(qx*qy - qw*qz), R02 = 2.f*(qx*qz + qw*qy);
        float R10 = 2.f*(qx*qy + qw*qz), R11 = 1.f - 2.f*(qx*qx + qz*qz), R12 = 2.f*(qy*qz - qw*qx);
        float R20 = 2.f*(qx*qz - qw*qy), R21 = 2.f*(qy*qz + qw*qx), R22 = 1.f - 2.f*(qx*qx + qy*qy);
        sR[0] = R00; sR[1] = R10; sR[2] = R20;
        sR[3] = R01; sR[4] = R11; sR[5] = R21;
        sR[6] = R02; sR[7] = R12; sR[8] = R22;
        sts[0] = t0; sts[1] = t1; sts[2] = t2;
        sts[3] = s0; sts[4] = s1; sts[5] = s2;
    }
    __syncthreads();
    if (tid < NPT) {
        float v0 = sscale[tid*3+0] * sts[3];
        float v1 = sscale[tid*3+1] * sts[4];
        float v2 = sscale[tid*3+2] * sts[5];
        skp[tid*3+0] = sR[0]*v0 + sR[1]*v1 + sR[2]*v2 + sts[0];
        skp[tid*3+1] = sR[3]*v0 + sR[4]*v1 + sR[5]*v2 + sts[1];
        skp[tid*3+2] = sR[6]*v0 + sR[7]*v1 + sR[8]*v2 + sts[2];
    }
    __syncthreads();
    if (tid < NPT * NC) {
        int pt = tid / NC, cam = tid % NC;
        float x = skp[pt*3+0], y = skp[pt*3+1], z = skp[pt*3+2];
        const float* P = proj + cam * 16;
        float px = P[0]*x + P[1]*y + P[2]*z  + P[3];
        float py = P[4]*x + P[5]*y + P[6]*z  + P[7];
        float pz = P[8]*x + P[9]*y + P[10]*z + P[11];
        pz = fmaxf(pz, 1e-5f);
        float u = (px / pz) / wh[cam*2+0];
        float v = (py / pz) / wh[cam*2+1];
        u = fminf(fmaxf(u, 0.f), 0.9999f);
        v = fminf(fmaxf(v, 0.f), 0.9999f);
        g_p2d[((size_t)a * (NPT*NC) + tid) * 2 + 0] = u;
        g_p2d[((size_t)a * (NPT*NC) + tid) * 2 + 1] = v;
    }
}

// ---------------------------------------------------------------------------
// 3/5) bf16 tensor-core GEMM: C = A @ Bm + bias (+ res)
//      mode 1: C := g_logits (A=inst)    mode 2: A := g_feats, C := Cp
// ---------------------------------------------------------------------------
__global__ void __launch_bounds__(256) gemm_bf16(
    const float* __restrict__ A, const float* __restrict__ Bm,
    const float* __restrict__ bias, const float* __restrict__ res,
    float* Cp, int N, int mode)
{
    float* C = (mode == 1) ? g_logits : Cp;
    if (mode == 2) A = g_feats;
    const int K = ED;
    __shared__ __nv_bfloat16 As[128][72];
    __shared__ __nv_bfloat16 Bst[64][72];

    int tid = threadIdx.x;
    int lane = tid & 31, w = tid >> 5;
    int wm = w & 3, wn = w >> 2;
    int m0 = blockIdx.y * 128, n0 = blockIdx.x * 64;
    int g = lane >> 2, t = lane & 3;

    float d[2][4][4];
#pragma unroll
    for (int mt = 0; mt < 2; mt++)
#pragma unroll
        for (int nt = 0; nt < 4; nt++)
#pragma unroll
            for (int r = 0; r < 4; r++) d[mt][nt][r] = 0.f;

    for (int k0 = 0; k0 < K; k0 += 64) {
#pragma unroll
        for (int i = 0; i < 32; i++) {
            int e = i * 256 + tid;
            int row = e >> 6, kk = e & 63;
            As[row][kk] = __float2bfloat16(A[(size_t)(m0 + row) * K + k0 + kk]);
        }
#pragma unroll
        for (int i = 0; i < 16; i++) {
            int e = i * 256 + tid;
            int kk = e >> 6, n = e & 63;
            Bst[n][kk] = __float2bfloat16(Bm[(size_t)(k0 + kk) * N + n0 + n]);
        }
        __syncthreads();
#pragma unroll
        for (int ks = 0; ks < 4; ks++) {
            int kb = ks * 16;
            unsigned a[2][4], b[4][2];
#pragma unroll
            for (int mt = 0; mt < 2; mt++) {
                int rb = wm * 32 + mt * 16;
                a[mt][0] = *(const unsigned*)&As[rb + g][kb + 2 * t];
                a[mt][1] = *(const unsigned*)&As[rb + g + 8][kb + 2 * t];
                a[mt][2] = *(const unsigned*)&As[rb + g][kb + 2 * t + 8];
                a[mt][3] = *(const unsigned*)&As[rb + g + 8][kb + 2 * t + 8];
            }
#pragma unroll
            for (int nt = 0; nt < 4; nt++) {
                int cb = wn * 32 + nt * 8;
                b[nt][0] = *(const unsigned*)&Bst[cb + g][kb + 2 * t];
                b[nt][1] = *(const unsigned*)&Bst[cb + g][kb + 2 * t + 8];
            }
#pragma unroll
            for (int mt = 0; mt < 2; mt++)
#pragma unroll
                for (int nt = 0; nt < 4; nt++)
                    asm volatile(
                        "mma.sync.aligned.m16n8k16.row.col.f32.bf16.bf16.f32 "
                        "{%0,%1,%2,%3}, {%4,%5,%6,%7}, {%8,%9}, {%0,%1,%2,%3};"
                        : "+f"(d[mt][nt][0]), "+f"(d[mt][nt][1]),
                          "+f"(d[mt][nt][2]), "+f"(d[mt][nt][3])
                        : "r"(a[mt][0]), "r"(a[mt][1]), "r"(a[mt][2]), "r"(a[mt][3]),
                          "r"(b[nt][0]), "r"(b[nt][1]));
        }
        __syncthreads();
    }
#pragma unroll
    for (int mt = 0; mt < 2; mt++) {
        int rb = m0 + wm * 32 + mt * 16;
#pragma unroll
        for (int nt = 0; nt < 4; nt++) {
            int n = n0 + wn * 32 + nt * 8 + 2 * t;
            float b0 = bias[n], b1 = bias[n + 1];
            float v00 = d[mt][nt][0] + b0, v01 = d[mt][nt][1] + b1;
            float v10 = d[mt][nt][2] + b0, v11 = d[mt][nt][3] + b1;
            if (res) {
                v00 += res[(size_t)(rb + g) * N + n];
                v01 += res[(size_t)(rb + g) * N + n + 1];
                v10 += res[(size_t)(rb + g + 8) * N + n];
                v11 += res[(size_t)(rb + g + 8) * N + n + 1];
            }
            C[(size_t)(rb + g) * N + n]         = v00;
            C[(size_t)(rb + g) * N + n + 1]     = v01;
            C[(size_t)(rb + g + 8) * N + n]     = v10;
            C[(size_t)(rb + g + 8) * N + n + 1] = v11;
        }
    }
}

// ---------------------------------------------------------------------------
// per-sample bilinear corner metadata (shared by count & fill passes)
// ---------------------------------------------------------------------------
struct Corners {
    unsigned o[4];   // 8-element-unit offsets (= uint4 units for fp16)
    float    w[4];   // bilinear weights (0 if invalid)
};

__device__ __forceinline__ Corners corner_meta(float2 p, int s) {
    int cam = s / (NL * NPT);
    int rr  = s % (NL * NPT);
    int lvl = rr / NPT;
    Corners r;
    int W = c_LW[lvl], H = c_LH[lvl];
    float x = p.x * (float)W - 0.5f;
    float y = p.y * (float)H - 0.5f;
    float xf = floorf(x), yf = floorf(y);
    float wx = x - xf, wy = y - yf;
    int x0 = (int)xf, y0 = (int)yf;
    int x1 = x0 + 1, y1 = y0 + 1;
    bool vx0 = (x0 >= 0) & (x0 < W);
    bool vx1 = (x1 >= 0) & (x1 < W);
    bool vy0 = (y0 >= 0) & (y0 < H);
    bool vy1 = (y1 >= 0) & (y1 < H);
    r.w[0] = (vx0 && vy0) ? (1.f - wx) * (1.f - wy) : 0.f;
    r.w[1] = (vx1 && vy0) ? wx * (1.f - wy) : 0.f;
    r.w[2] = (vx0 && vy1) ? (1.f - wx) * wy : 0.f;
    r.w[3] = (vx1 && vy1) ? wx * wy : 0.f;
    int x0c = min(max(x0, 0), W - 1), x1c = min(max(x1, 0), W - 1);
    int y0c = min(max(y0, 0), H - 1), y1c = min(max(y1, 0), H - 1);
    unsigned lb = c_LB[lvl];
    unsigned rowb = (unsigned)(cam * H);
    // element offset = lb + texel*256; 8-element units = >>3 (uint4 for fp16)
    r.o[0] = (lb + ((rowb + (unsigned)y0c) * (unsigned)W + (unsigned)x0c) * 256u) >> 3;
    r.o[1] = (lb + ((rowb + (unsigned)y0c) * (unsigned)W + (unsigned)x1c) * 256u) >> 3;
    r.o[2] = (lb + ((rowb + (unsigned)y1c) * (unsigned)W + (unsigned)x0c) * 256u) >> 3;
    r.o[3] = (lb + ((rowb + (unsigned)y1c) * (unsigned)W + (unsigned)x1c) * 256u) >> 3;
    return r;
}

// ---------------------------------------------------------------------------
// 4) Fused softmax + compacted bilinear aggregation (fp16 features, half2 MAC).
//    Hot loop: warp-per-corner; lane loads uint4 = 8 fp16 channels (LDG.128),
//    feeding 4 hfma2 directly — ZERO decode converts.
// ---------------------------------------------------------------------------
__global__ void __launch_bounds__(256) agg_kernel() {
    int a = blockIdx.x;
    int tid = threadIdx.x;
    int lane = tid & 31, warp = tid >> 5;

    __shared__ float  sw[NG * NSAMPP];            // softmaxed weights, [g][s]
    __shared__ float2 sp2[NPT * NC];
    __shared__ __align__(8) uint2 flist[MAXCOR];  // (off, s<<16 | w_half)
    __shared__ int scnt[320];
    __shared__ int sbase[NSAMP];
    __shared__ int sT;
    __shared__ __align__(16) float spart[8 * ED];

    const float* lrow = g_logits + (size_t)a * NWTS;
    for (int i = tid; i < NWTS; i += 256) {
        int s = i >> 3, g = i & 7;
        sw[g * NSAMPP + s] = lrow[i];
    }
    if (tid < NPT * NC) sp2[tid] = ((const float2*)g_p2d)[(size_t)a * (NPT*NC) + tid];
    if (tid >= NSAMP && tid < 320) scnt[tid] = 0;
    __syncthreads();

    // per-group softmax over 312 entries (warp g handles group g; conflict-free)
    {
        float* swg = sw + warp * NSAMPP;
        float m = -1e30f;
        for (int i = lane; i < NSAMP; i += 32) m = fmaxf(m, swg[i]);
#pragma unroll
        for (int o = 16; o > 0; o >>= 1) m = fmaxf(m, __shfl_xor_sync(0xffffffffu, m, o));
        float ssum = 0.f;
        for (int i = lane; i < NSAMP; i += 32) {
            float e = __expf(swg[i] - m);
            swg[i] = e;
            ssum += e;
        }
#pragma unroll
        for (int o = 16; o > 0; o >>= 1) ssum += __shfl_xor_sync(0xffffffffu, ssum, o);
        float inv = 1.f / ssum;
        for (int i = lane; i < NSAMP; i += 32) swg[i] *= inv;
    }

    // pass 1: per-sample valid-corner counts
    for (int s = tid; s < NSAMP; s += 256) {
        int pt = (s % (NL * NPT)) % NPT, cam = s / (NL * NPT);
        Corners cr = corner_meta(sp2[pt * NC + cam], s);
        scnt[s] = (cr.w[0] != 0.f) + (cr.w[1] != 0.f) + (cr.w[2] != 0.f) + (cr.w[3] != 0.f);
    }
    __syncthreads();

    // deterministic exclusive scan over 312 counts
    if (tid < 32) {
        int l = tid;
        int tot = 0;
#pragma unroll
        for (int k = 0; k < 10; k++) {
            int s = l * 10 + k;
            tot += (s < NSAMP) ? scnt[s] : 0;
        }
        int inc = tot;
#pragma unroll
        for (int o = 1; o < 32; o <<= 1) {
            int v = __shfl_up_sync(0xffffffffu, inc, o);
            if (l >= o) inc += v;
        }
        int run = inc - tot;
#pragma unroll
        for (int k = 0; k < 10; k++) {
            int s = l * 10 + k;
            if (s < NSAMP) { sbase[s] = run; run += scnt[s]; }
        }
        if (l == 31) sT = run;
    }
    __syncthreads();

    // pass 2: fill compacted corner list (weight stored as half)
    for (int s = tid; s < NSAMP; s += 256) {
        int pt = (s % (NL * NPT)) % NPT, cam = s / (NL * NPT);
        Corners cr = corner_meta(sp2[pt * NC + cam], s);
        int b = sbase[s];
        unsigned shi = ((unsigned)s) << 16;
#pragma unroll
        for (int k = 0; k < 4; k++) {
            if (cr.w[k] != 0.f) {
                unsigned wbits = (unsigned)__half_as_ushort(__float2half_rn(cr.w[k]));
                flist[b] = make_uint2(cr.o[k], shi | wbits);
                b++;
            }
        }
    }
    __syncthreads();

    const int T = sT;
    int g = lane >> 2;                    // group of this 8-channel slab
    const float* swg = sw + g * NSAMPP;
    __half2 hz = __float2half2_rn(0.f);
    __half2 h0 = hz, h1 = hz, h2a = hz, h3 = hz;
    const uint4* __restrict__ F16 = (const uint4*)g_f16;
#pragma unroll 4
    for (int j = warp; j < T; j += 8) {
        uint2 e = flist[j];                                   // broadcast LDS.64
        float w = swg[e.y >> 16] *
                  __half2float(__ushort_as_half((unsigned short)(e.y & 0xffffu)));
        __half2 wh = __float2half2_rn(w);
        uint4 u = __ldg(F16 + e.x + lane);                    // 8 fp16 channels
        h0  = __hfma2(wh, *reinterpret_cast<__half2*>(&u.x), h0);
        h1  = __hfma2(wh, *reinterpret_cast<__half2*>(&u.y), h1);
        h2a = __hfma2(wh, *reinterpret_cast<__half2*>(&u.z), h2a);
        h3  = __hfma2(wh, *reinterpret_cast<__half2*>(&u.w), h3);
    }
    {
        float2 f0 = __half22float2(h0), f1 = __half22float2(h1);
        float2 f2 = __half22float2(h2a), f3 = __half22float2(h3);
        float4* sp4 = (float4*)&spart[warp * ED + lane * 8];
        sp4[0] = make_float4(f0.x, f0.y, f1.x, f1.y);
        sp4[1] = make_float4(f2.x, f2.y, f3.x, f3.y);
    }
    __syncthreads();
    {
        int ch = tid;
        float r = spart[ch];
#pragma unroll
        for (int p = 1; p < 8; p++) r += spart[p * ED + ch];
        g_feats[(size_t)a * ED + ch] = r;
    }
}

// ---------------------------------------------------------------------------
// launch — inputs bound by unique element counts (order-proof); single stream
// ---------------------------------------------------------------------------
extern "C" void kernel_launch(void* const* d_in, const int* in_sizes, int n_in,
                              void* d_out, int out_size) {
    const float* inst = 0; const float* anchor = 0;
    const float* feat[4] = {0,0,0,0};
    const float* proj = 0; const float* wh = 0;
    const float* Wl = 0; const float* bl = 0;
    const float* Ww = 0; const float* bw = 0;
    const float* Wo = 0; const float* bo = 0;

    for (int i = 0; i < n_in; i++) {
        const float* p = (const float*)d_in[i];
        switch (in_sizes[i]) {
            case 1048576:  inst    = p; break;
            case 45056:    anchor  = p; break;
            case 17301504: feat[0] = p; break;
            case 4325376:  feat[1] = p; break;
            case 1081344:  feat[2] = p; break;
            case 270336:   feat[3] = p; break;
            case 96:       proj    = p; break;
            case 12:       wh      = p; break;
            case 4608:     Wl      = p; break;
            case 18:       bl      = p; break;
            case 638976:   Ww      = p; break;
            case 2496:     bw      = p; break;
            case 65536:    Wo      = p; break;
            case 256:      bo      = p; break;
            default: break;
        }
    }
    float* out = (float*)d_out;

    // 1) fused transpose+fp16 convert (single launch, all 4 levels)
    {
        dim3 grid(468, ED / 32, NC);
        dim3 block(32, 8);
        transpose_all<<<grid, block>>>(feat[0], feat[1], feat[2], feat[3]);
    }

    // 2) per-anchor setup
    setup_kernel<<<NA, 128>>>(inst, anchor, proj, wh, Wl, bl);

    // 3) weight logits GEMM on tensor cores -> g_logits (mode 1)
    {
        dim3 grid(NWTS / 64, NA / 128);
        gemm_bf16<<<grid, 256>>>(inst, Ww, bw, nullptr, nullptr, NWTS, 1);
    }

    // 4) fused softmax + compacted aggregation (fp16 features)
    agg_kernel<<<NA, 256>>>();

    // 5) output GEMM on tensor cores: g_feats @ Wo + bo + inst -> d_out (mode 2)
    {
        dim3 grid(ED / 64, NA / 128);
        gemm_bf16<<<grid, 256>>>(nullptr, Wo, bo, inst, out, ED, 2);
    }
}

// round 16
// speedup vs baseline: 2.4214x; 1.1712x over previous
#include <cuda_runtime.h>
#include <cuda_fp16.h>
#include <cuda_bf16.h>
#include <cuda_fp8.h>
#include <math.h>
#include <stdint.h>

// ---------------------------------------------------------------------------
// Problem constants (fixed by the reference)
// ---------------------------------------------------------------------------
#define NA        4096
#define ED        256      // EMBED_DIMS
#define NG        8        // NUM_GROUPS
#define GD        32       // GROUP_DIMS
#define NL        4        // NUM_LEVELS
#define NC        6        // NUM_CAMS
#define NPT       13       // NUM_PTS (7 fixed + 6 learnable)
#define NSAMP     312      // NC*NL*NPT
#define NSAMPP    313      // padded (bank destagger)
#define NWTS      2496     // NSAMP*NG
#define MAXCOR    1280     // >= NSAMP*4

// level dims
__constant__ int   c_LW[4] = {176, 88, 44, 22};
__constant__ int   c_LH[4] = {64, 32, 16, 8};
__constant__ unsigned c_LB[4] = {0u, 17301504u, 21626880u, 22708224u};  // byte offsets (1B/elem)
__constant__ int   c_HW[4] = {11264, 2816, 704, 176};
__constant__ int   c_tileBase[5] = {0, 352, 440, 462, 468};  // cumulative 32-wide hw tiles

__constant__ float c_fix[21] = {
    0.f,0.f,0.f,  0.45f,0.f,0.f,  -0.45f,0.f,0.f,
    0.f,0.45f,0.f, 0.f,-0.45f,0.f, 0.f,0.f,0.45f, 0.f,0.f,-0.45f
};

// ---------------------------------------------------------------------------
// Scratch (static __device__ — device-code references ONLY; host-side address
// of a __device__ symbol is the host shadow and silently "works" via ATS).
// ---------------------------------------------------------------------------
__device__ __align__(16) unsigned char g_f8[22978560]; // 4 levels, NHWC, fp8 e4m3
__device__ float  g_logits[NA * NWTS];      // weight logits (softmaxed in agg)
__device__ float  g_p2d[NA * NPT * NC * 2]; // projected points
__device__ float  g_feats[NA * ED];         // aggregated features

// ---------------------------------------------------------------------------
// 1) Fused CHW -> HWC transpose + fp32->fp8(e4m3), ALL levels, 1 launch.
//    Stores vectorized as uchar4 (4 channels/thread) — 4x fewer STGs.
// ---------------------------------------------------------------------------
__global__ void transpose_all(const float* __restrict__ f0, const float* __restrict__ f1,
                              const float* __restrict__ f2, const float* __restrict__ f3) {
    __shared__ float tile[32][33];
    int bx = blockIdx.x;
    int lvl = 0;
#pragma unroll
    for (int l = 1; l < 4; l++) if (bx >= c_tileBase[l]) lvl = l;
    const float* src = (lvl == 0) ? f0 : (lvl == 1) ? f1 : (lvl == 2) ? f2 : f3;
    int HW = c_HW[lvl];
    unsigned dst_base = c_LB[lvl];

    int cam = blockIdx.z;
    int hw0 = (bx - c_tileBase[lvl]) * 32;
    int c0  = blockIdx.y * 32;
    const float* s = src + (size_t)cam * ED * HW;
    unsigned char* d = g_f8 + dst_base + (size_t)cam * HW * ED;
    int tx = threadIdx.x, ty = threadIdx.y;
    int tid = ty * 32 + tx;
#pragma unroll
    for (int i = 0; i < 32; i += 8) {
        int c  = c0 + ty + i;
        int hw = hw0 + tx;
        float v = (hw < HW) ? s[(size_t)c * HW + hw] : 0.f;
        tile[ty + i][tx] = v;
    }
    __syncthreads();
    // store: thread -> (hw row, 4-channel group); conflict-free smem reads
    {
        int hwl = tid >> 3;       // 0..31
        int cg  = tid & 7;        // 0..7 (4 channels each)
        int hw  = hw0 + hwl;
        if (hw < HW) {
            uchar4 v;
            v.x = (unsigned char)__nv_cvt_float_to_fp8(tile[cg*4+0][hwl], __NV_SATFINITE, __NV_E4M3);
            v.y = (unsigned char)__nv_cvt_float_to_fp8(tile[cg*4+1][hwl], __NV_SATFINITE, __NV_E4M3);
            v.z = (unsigned char)__nv_cvt_float_to_fp8(tile[cg*4+2][hwl], __NV_SATFINITE, __NV_E4M3);
            v.w = (unsigned char)__nv_cvt_float_to_fp8(tile[cg*4+3][hwl], __NV_SATFINITE, __NV_E4M3);
            *reinterpret_cast<uchar4*>(d + (size_t)hw * ED + c0 + cg * 4) = v;
        }
    }
}

// ---------------------------------------------------------------------------
// 2) Per-anchor setup: learnable points, rotation, projection -> g_p2d
// ---------------------------------------------------------------------------
__global__ void __launch_bounds__(128) setup_kernel(
    const float* __restrict__ inst, const float* __restrict__ anchor,
    const float* __restrict__ proj, const float* __restrict__ wh,
    const float* __restrict__ Wl, const float* __restrict__ bl)
{
    int a = blockIdx.x;
    int tid = threadIdx.x;
    __shared__ float sif[ED];
    __shared__ float sscale[NPT * 3];
    __shared__ float skp[NPT * 3];
    __shared__ float sR[9];
    __shared__ float sts[6];

    const float* f = inst + (size_t)a * ED;
    sif[tid]       = f[tid];
    sif[tid + 128] = f[tid + 128];
    if (tid < 21) sscale[tid] = c_fix[tid];
    __syncthreads();

    const float* an = anchor + (size_t)a * 11;

    if (tid < 18) {
        float acc = bl[tid];
#pragma unroll 8
        for (int i = 0; i < ED; i++) acc = fmaf(sif[i], Wl[i * 18 + tid], acc);
        acc = fminf(fmaxf(acc, -9.21f), 9.21f);
        float sg = 1.f / (1.f + expf(-acc));
        sscale[21 + tid] = sg - 0.5f;
    }
    if (tid == 32) {
        float t0 = an[0], t1 = an[1], t2 = an[2];
        float s0 = an[3], s1 = an[4], s2 = an[5];
        float qw = an[6], qx = an[7], qy = an[8], qz = an[9];
        float inv = rsqrtf(qw*qw + qx*qx + qy*qy + qz*qz);
        qw *= inv; qx *= inv; qy *= inv; qz *= inv;
        float R00 = 1.f - 2.f*(qy*qy + qz*qz), R01 = 2.f*(qx*qy - qw*qz), R02 = 2.f*(qx*qz + qw*qy);
        float R10 = 2.f*(qx*qy + qw*qz), R11 = 1.f - 2.f*(qx*qx + qz*qz), R12 = 2.f*(qy*qz - qw*qx);
        float R20 = 2.f*(qx*qz - qw*qy), R21 = 2.f*(qy*qz + qw*qx), R22 = 1.f - 2.f*(qx*qx + qy*qy);
        sR[0] = R00; sR[1] = R10; sR[2] = R20;
        sR[3] = R01; sR[4] = R11; sR[5] = R21;
        sR[6] = R02; sR[7] = R12; sR[8] = R22;
        sts[0] = t0; sts[1] = t1; sts[2] = t2;
        sts[3] = s0; sts[4] = s1; sts[5] = s2;
    }
    __syncthreads();
    if (tid < NPT) {
        float v0 = sscale[tid*3+0] * sts[3];
        float v1 = sscale[tid*3+1] * sts[4];
        float v2 = sscale[tid*3+2] * sts[5];
        skp[tid*3+0] = sR[0]*v0 + sR[1]*v1 + sR[2]*v2 + sts[0];
        skp[tid*3+1] = sR[3]*v0 + sR[4]*v1 + sR[5]*v2 + sts[1];
        skp[tid*3+2] = sR[6]*v0 + sR[7]*v1 + sR[8]*v2 + sts[2];
    }
    __syncthreads();
    if (tid < NPT * NC) {
        int pt = tid / NC, cam = tid % NC;
        float x = skp[pt*3+0], y = skp[pt*3+1], z = skp[pt*3+2];
        const float* P = proj + cam * 16;
        float px = P[0]*x + P[1]*y + P[2]*z  + P[3];
        float py = P[4]*x + P[5]*y + P[6]*z  + P[7];
        float pz = P[8]*x + P[9]*y + P[10]*z + P[11];
        pz = fmaxf(pz, 1e-5f);
        float u = (px / pz) / wh[cam*2+0];
        float v = (py / pz) / wh[cam*2+1];
        u = fminf(fmaxf(u, 0.f), 0.9999f);
        v = fminf(fmaxf(v, 0.f), 0.9999f);
        g_p2d[((size_t)a * (NPT*NC) + tid) * 2 + 0] = u;
        g_p2d[((size_t)a * (NPT*NC) + tid) * 2 + 1] = v;
    }
}

// ---------------------------------------------------------------------------
// 3) Logits GEMM, bf16 tensor cores, BM=128 BN=96 (fewer A re-reads -> less L2).
//    8 warps as 4(m) x 2(n); warp tile 32m x 48n.
// ---------------------------------------------------------------------------
__global__ void __launch_bounds__(256) gemm_logits96(
    const float* __restrict__ A, const float* __restrict__ Bm,
    const float* __restrict__ bias)
{
    float* C = g_logits;
    const int N = NWTS, K = ED;
    __shared__ __nv_bfloat16 As[128][72];
    __shared__ __nv_bfloat16 Bst[96][72];

    int tid = threadIdx.x;
    int lane = tid & 31, w = tid >> 5;
    int wm = w & 3, wn = w >> 2;
    int m0 = blockIdx.y * 128, n0 = blockIdx.x * 96;
    int g = lane >> 2, t = lane & 3;

    float d[2][6][4];
#pragma unroll
    for (int mt = 0; mt < 2; mt++)
#pragma unroll
        for (int nt = 0; nt < 6; nt++)
#pragma unroll
            for (int r = 0; r < 4; r++) d[mt][nt][r] = 0.f;

    for (int k0 = 0; k0 < K; k0 += 64) {
#pragma unroll
        for (int i = 0; i < 32; i++) {
            int e = i * 256 + tid;
            int row = e >> 6, kk = e & 63;
            As[row][kk] = __float2bfloat16(A[(size_t)(m0 + row) * K + k0 + kk]);
        }
        // B tile: 64(k) x 96(n) = 6144 elems, 24 per thread
#pragma unroll
        for (int i = 0; i < 24; i++) {
            int e = i * 256 + tid;
            int kk = e / 96, n = e % 96;
            Bst[n][kk] = __float2bfloat16(Bm[(size_t)(k0 + kk) * N + n0 + n]);
        }
        __syncthreads();
#pragma unroll
        for (int ks = 0; ks < 4; ks++) {
            int kb = ks * 16;
            unsigned a[2][4], b[6][2];
#pragma unroll
            for (int mt = 0; mt < 2; mt++) {
                int rb = wm * 32 + mt * 16;
                a[mt][0] = *(const unsigned*)&As[rb + g][kb + 2 * t];
                a[mt][1] = *(const unsigned*)&As[rb + g + 8][kb + 2 * t];
                a[mt][2] = *(const unsigned*)&As[rb + g][kb + 2 * t + 8];
                a[mt][3] = *(const unsigned*)&As[rb + g + 8][kb + 2 * t + 8];
            }
#pragma unroll
            for (int nt = 0; nt < 6; nt++) {
                int cb = wn * 48 + nt * 8;
                b[nt][0] = *(const unsigned*)&Bst[cb + g][kb + 2 * t];
                b[nt][1] = *(const unsigned*)&Bst[cb + g][kb + 2 * t + 8];
            }
#pragma unroll
            for (int mt = 0; mt < 2; mt++)
#pragma unroll
                for (int nt = 0; nt < 6; nt++)
                    asm volatile(
                        "mma.sync.aligned.m16n8k16.row.col.f32.bf16.bf16.f32 "
                        "{%0,%1,%2,%3}, {%4,%5,%6,%7}, {%8,%9}, {%0,%1,%2,%3};"
                        : "+f"(d[mt][nt][0]), "+f"(d[mt][nt][1]),
                          "+f"(d[mt][nt][2]), "+f"(d[mt][nt][3])
                        : "r"(a[mt][0]), "r"(a[mt][1]), "r"(a[mt][2]), "r"(a[mt][3]),
                          "r"(b[nt][0]), "r"(b[nt][1]));
        }
        __syncthreads();
    }
#pragma unroll
    for (int mt = 0; mt < 2; mt++) {
        int rb = m0 + wm * 32 + mt * 16;
#pragma unroll
        for (int nt = 0; nt < 6; nt++) {
            int n = n0 + wn * 48 + nt * 8 + 2 * t;
            float b0 = bias[n], b1 = bias[n + 1];
            C[(size_t)(rb + g) * N + n]         = d[mt][nt][0] + b0;
            C[(size_t)(rb + g) * N + n + 1]     = d[mt][nt][1] + b1;
            C[(size_t)(rb + g + 8) * N + n]     = d[mt][nt][2] + b0;
            C[(size_t)(rb + g + 8) * N + n + 1] = d[mt][nt][3] + b1;
        }
    }
}

// ---------------------------------------------------------------------------
// 5) Out GEMM (bf16 tensor cores, BM=128 BN=64): d_out = g_feats @ Wo + bo + inst
// ---------------------------------------------------------------------------
__global__ void __launch_bounds__(256) gemm_bf16_out(
    const float* __restrict__ Bm, const float* __restrict__ bias,
    const float* __restrict__ res, float* __restrict__ C)
{
    const float* A = g_feats;
    const int N = ED, K = ED;
    __shared__ __nv_bfloat16 As[128][72];
    __shared__ __nv_bfloat16 Bst[64][72];

    int tid = threadIdx.x;
    int lane = tid & 31, w = tid >> 5;
    int wm = w & 3, wn = w >> 2;
    int m0 = blockIdx.y * 128, n0 = blockIdx.x * 64;
    int g = lane >> 2, t = lane & 3;

    float d[2][4][4];
#pragma unroll
    for (int mt = 0; mt < 2; mt++)
#pragma unroll
        for (int nt = 0; nt < 4; nt++)
#pragma unroll
            for (int r = 0; r < 4; r++) d[mt][nt][r] = 0.f;

    for (int k0 = 0; k0 < K; k0 += 64) {
#pragma unroll
        for (int i = 0; i < 32; i++) {
            int e = i * 256 + tid;
            int row = e >> 6, kk = e & 63;
            As[row][kk] = __float2bfloat16(A[(size_t)(m0 + row) * K + k0 + kk]);
        }
#pragma unroll
        for (int i = 0; i < 16; i++) {
            int e = i * 256 + tid;
            int kk = e >> 6, n = e & 63;
            Bst[n][kk] = __float2bfloat16(Bm[(size_t)(k0 + kk) * N + n0 + n]);
        }
        __syncthreads();
#pragma unroll
        for (int ks = 0; ks < 4; ks++) {
            int kb = ks * 16;
            unsigned a[2][4], b[4][2];
#pragma unroll
            for (int mt = 0; mt < 2; mt++) {
                int rb = wm * 32 + mt * 16;
                a[mt][0] = *(const unsigned*)&As[rb + g][kb + 2 * t];
                a[mt][1] = *(const unsigned*)&As[rb + g + 8][kb + 2 * t];
                a[mt][2] = *(const unsigned*)&As[rb + g][kb + 2 * t + 8];
                a[mt][3] = *(const unsigned*)&As[rb + g + 8][kb + 2 * t + 8];
            }
#pragma unroll
            for (int nt = 0; nt < 4; nt++) {
                int cb = wn * 32 + nt * 8;
                b[nt][0] = *(const unsigned*)&Bst[cb + g][kb + 2 * t];
                b[nt][1] = *(const unsigned*)&Bst[cb + g][kb + 2 * t + 8];
            }
#pragma unroll
            for (int mt = 0; mt < 2; mt++)
#pragma unroll
                for (int nt = 0; nt < 4; nt++)
                    asm volatile(
                        "mma.sync.aligned.m16n8k16.row.col.f32.bf16.bf16.f32 "
                        "{%0,%1,%2,%3}, {%4,%5,%6,%7}, {%8,%9}, {%0,%1,%2,%3};"
                        : "+f"(d[mt][nt][0]), "+f"(d[mt][nt][1]),
                          "+f"(d[mt][nt][2]), "+f"(d[mt][nt][3])
                        : "r"(a[mt][0]), "r"(a[mt][1]), "r"(a[mt][2]), "r"(a[mt][3]),
                          "r"(b[nt][0]), "r"(b[nt][1]));
        }
        __syncthreads();
    }
#pragma unroll
    for (int mt = 0; mt < 2; mt++) {
        int rb = m0 + wm * 32 + mt * 16;
#pragma unroll
        for (int nt = 0; nt < 4; nt++) {
            int n = n0 + wn * 32 + nt * 8 + 2 * t;
            float b0 = bias[n], b1 = bias[n + 1];
            float v00 = d[mt][nt][0] + b0 + res[(size_t)(rb + g) * N + n];
            float v01 = d[mt][nt][1] + b1 + res[(size_t)(rb + g) * N + n + 1];
            float v10 = d[mt][nt][2] + b0 + res[(size_t)(rb + g + 8) * N + n];
            float v11 = d[mt][nt][3] + b1 + res[(size_t)(rb + g + 8) * N + n + 1];
            C[(size_t)(rb + g) * N + n]         = v00;
            C[(size_t)(rb + g) * N + n + 1]     = v01;
            C[(size_t)(rb + g + 8) * N + n]     = v10;
            C[(size_t)(rb + g + 8) * N + n + 1] = v11;
        }
    }
}

// ---------------------------------------------------------------------------
// per-sample bilinear corner metadata (shared by count & fill passes)
// ---------------------------------------------------------------------------
struct Corners {
    unsigned o[4];   // uint2-unit offsets (8 fp8 bytes per unit)
    float    w[4];   // bilinear weights (0 if invalid)
};

__device__ __forceinline__ Corners corner_meta(float2 p, int s) {
    int cam = s / (NL * NPT);
    int rr  = s % (NL * NPT);
    int lvl = rr / NPT;
    Corners r;
    int W = c_LW[lvl], H = c_LH[lvl];
    float x = p.x * (float)W - 0.5f;
    float y = p.y * (float)H - 0.5f;
    float xf = floorf(x), yf = floorf(y);
    float wx = x - xf, wy = y - yf;
    int x0 = (int)xf, y0 = (int)yf;
    int x1 = x0 + 1, y1 = y0 + 1;
    bool vx0 = (x0 >= 0) & (x0 < W);
    bool vx1 = (x1 >= 0) & (x1 < W);
    bool vy0 = (y0 >= 0) & (y0 < H);
    bool vy1 = (y1 >= 0) & (y1 < H);
    r.w[0] = (vx0 && vy0) ? (1.f - wx) * (1.f - wy) : 0.f;
    r.w[1] = (vx1 && vy0) ? wx * (1.f - wy) : 0.f;
    r.w[2] = (vx0 && vy1) ? (1.f - wx) * wy : 0.f;
    r.w[3] = (vx1 && vy1) ? wx * wy : 0.f;
    int x0c = min(max(x0, 0), W - 1), x1c = min(max(x1, 0), W - 1);
    int y0c = min(max(y0, 0), H - 1), y1c = min(max(y1, 0), H - 1);
    unsigned lb = c_LB[lvl];
    unsigned rowb = (unsigned)(cam * H);
    r.o[0] = (lb + ((rowb + (unsigned)y0c) * (unsigned)W + (unsigned)x0c) * 256u) >> 3;
    r.o[1] = (lb + ((rowb + (unsigned)y0c) * (unsigned)W + (unsigned)x1c) * 256u) >> 3;
    r.o[2] = (lb + ((rowb + (unsigned)y1c) * (unsigned)W + (unsigned)x0c) * 256u) >> 3;
    r.o[3] = (lb + ((rowb + (unsigned)y1c) * (unsigned)W + (unsigned)x1c) * 256u) >> 3;
    return r;
}

// ---------------------------------------------------------------------------
// 4) Fused softmax + compacted bilinear aggregation (fp8, half2 MAC).
//    R13-proven version, byte-identical.
// ---------------------------------------------------------------------------
__global__ void __launch_bounds__(256) agg_kernel() {
    int a = blockIdx.x;
    int tid = threadIdx.x;
    int lane = tid & 31, warp = tid >> 5;

    __shared__ float  sw[NG * NSAMPP];            // softmaxed weights, [g][s]
    __shared__ float2 sp2[NPT * NC];
    __shared__ __align__(8) uint2 flist[MAXCOR];  // (off8, s<<16 | w_half)
    __shared__ int scnt[320];
    __shared__ int sbase[NSAMP];
    __shared__ int sT;
    __shared__ __align__(16) float spart[8 * ED];

    const float* lrow = g_logits + (size_t)a * NWTS;
    for (int i = tid; i < NWTS; i += 256) {
        int s = i >> 3, g = i & 7;
        sw[g * NSAMPP + s] = lrow[i];
    }
    if (tid < NPT * NC) sp2[tid] = ((const float2*)g_p2d)[(size_t)a * (NPT*NC) + tid];
    if (tid >= NSAMP && tid < 320) scnt[tid] = 0;
    __syncthreads();

    // per-group softmax over 312 entries (warp g handles group g; conflict-free)
    {
        float* swg = sw + warp * NSAMPP;
        float m = -1e30f;
        for (int i = lane; i < NSAMP; i += 32) m = fmaxf(m, swg[i]);
#pragma unroll
        for (int o = 16; o > 0; o >>= 1) m = fmaxf(m, __shfl_xor_sync(0xffffffffu, m, o));
        float ssum = 0.f;
        for (int i = lane; i < NSAMP; i += 32) {
            float e = __expf(swg[i] - m);
            swg[i] = e;
            ssum += e;
        }
#pragma unroll
        for (int o = 16; o > 0; o >>= 1) ssum += __shfl_xor_sync(0xffffffffu, ssum, o);
        float inv = 1.f / ssum;
        for (int i = lane; i < NSAMP; i += 32) swg[i] *= inv;
    }

    // pass 1: per-sample valid-corner counts
    for (int s = tid; s < NSAMP; s += 256) {
        int pt = (s % (NL * NPT)) % NPT, cam = s / (NL * NPT);
        Corners cr = corner_meta(sp2[pt * NC + cam], s);
        scnt[s] = (cr.w[0] != 0.f) + (cr.w[1] != 0.f) + (cr.w[2] != 0.f) + (cr.w[3] != 0.f);
    }
    __syncthreads();

    // deterministic exclusive scan over 312 counts
    if (tid < 32) {
        int l = tid;
        int tot = 0;
#pragma unroll
        for (int k = 0; k < 10; k++) {
            int s = l * 10 + k;
            tot += (s < NSAMP) ? scnt[s] : 0;
        }
        int inc = tot;
#pragma unroll
        for (int o = 1; o < 32; o <<= 1) {
            int v = __shfl_up_sync(0xffffffffu, inc, o);
            if (l >= o) inc += v;
        }
        int run = inc - tot;
#pragma unroll
        for (int k = 0; k < 10; k++) {
            int s = l * 10 + k;
            if (s < NSAMP) { sbase[s] = run; run += scnt[s]; }
        }
        if (l == 31) sT = run;
    }
    __syncthreads();

    // pass 2: fill compacted corner list (weight stored as half)
    for (int s = tid; s < NSAMP; s += 256) {
        int pt = (s % (NL * NPT)) % NPT, cam = s / (NL * NPT);
        Corners cr = corner_meta(sp2[pt * NC + cam], s);
        int b = sbase[s];
        unsigned shi = ((unsigned)s) << 16;
#pragma unroll
        for (int k = 0; k < 4; k++) {
            if (cr.w[k] != 0.f) {
                unsigned wbits = (unsigned)__half_as_ushort(__float2half_rn(cr.w[k]));
                flist[b] = make_uint2(cr.o[k], shi | wbits);
                b++;
            }
        }
    }
    __syncthreads();

    const int T = sT;
    int g = lane >> 2;                    // group of this 8-channel slab
    const float* swg = sw + g * NSAMPP;
    __half2 hz = __float2half2_rn(0.f);
    __half2 h0 = hz, h1 = hz, h2a = hz, h3 = hz;
    const uint2* __restrict__ F8 = (const uint2*)g_f8;
#pragma unroll 4
    for (int j = warp; j < T; j += 8) {
        uint2 e = flist[j];                                   // broadcast LDS.64
        float w = swg[e.y >> 16] *
                  __half2float(__ushort_as_half((unsigned short)(e.y & 0xffffu)));
        __half2 wh = __float2half2_rn(w);
        uint2 u = __ldg(F8 + e.x + lane);
        __half2_raw r0 = __nv_cvt_fp8x2_to_halfraw2((__nv_fp8x2_storage_t)(u.x & 0xffffu), __NV_E4M3);
        __half2_raw r1 = __nv_cvt_fp8x2_to_halfraw2((__nv_fp8x2_storage_t)(u.x >> 16), __NV_E4M3);
        __half2_raw r2 = __nv_cvt_fp8x2_to_halfraw2((__nv_fp8x2_storage_t)(u.y & 0xffffu), __NV_E4M3);
        __half2_raw r3 = __nv_cvt_fp8x2_to_halfraw2((__nv_fp8x2_storage_t)(u.y >> 16), __NV_E4M3);
        h0  = __hfma2(wh, *reinterpret_cast<__half2*>(&r0), h0);
        h1  = __hfma2(wh, *reinterpret_cast<__half2*>(&r1), h1);
        h2a = __hfma2(wh, *reinterpret_cast<__half2*>(&r2), h2a);
        h3  = __hfma2(wh, *reinterpret_cast<__half2*>(&r3), h3);
    }
    {
        float2 f0 = __half22float2(h0), f1 = __half22float2(h1);
        float2 f2 = __half22float2(h2a), f3 = __half22float2(h3);
        float4* sp4 = (float4*)&spart[warp * ED + lane * 8];
        sp4[0] = make_float4(f0.x, f0.y, f1.x, f1.y);
        sp4[1] = make_float4(f2.x, f2.y, f3.x, f3.y);
    }
    __syncthreads();
    {
        int ch = tid;
        float r = spart[ch];
#pragma unroll
        for (int p = 1; p < 8; p++) r += spart[p * ED + ch];
        g_feats[(size_t)a * ED + ch] = r;
    }
}

// ---------------------------------------------------------------------------
// launch — inputs bound by unique element counts (order-proof); single stream
// ---------------------------------------------------------------------------
extern "C" void kernel_launch(void* const* d_in, const int* in_sizes, int n_in,
                              void* d_out, int out_size) {
    const float* inst = 0; const float* anchor = 0;
    const float* feat[4] = {0,0,0,0};
    const float* proj = 0; const float* wh = 0;
    const float* Wl = 0; const float* bl = 0;
    const float* Ww = 0; const float* bw = 0;
    const float* Wo = 0; const float* bo = 0;

    for (int i = 0; i < n_in; i++) {
        const float* p = (const float*)d_in[i];
        switch (in_sizes[i]) {
            case 1048576:  inst    = p; break;
            case 45056:    anchor  = p; break;
            case 17301504: feat[0] = p; break;
            case 4325376:  feat[1] = p; break;
            case 1081344:  feat[2] = p; break;
            case 270336:   feat[3] = p; break;
            case 96:       proj    = p; break;
            case 12:       wh      = p; break;
            case 4608:     Wl      = p; break;
            case 18:       bl      = p; break;
            case 638976:   Ww      = p; break;
            case 2496:     bw      = p; break;
            case 65536:    Wo      = p; break;
            case 256:      bo      = p; break;
            default: break;
        }
    }
    float* out = (float*)d_out;

    // 1) fused transpose+fp8 convert (single launch, all 4 levels)
    {
        dim3 grid(468, ED / 32, NC);
        dim3 block(32, 8);
        transpose_all<<<grid, block>>>(feat[0], feat[1], feat[2], feat[3]);
    }

    // 2) per-anchor setup
    setup_kernel<<<NA, 128>>>(inst, anchor, proj, wh, Wl, bl);

    // 3) weight logits GEMM (BM=128, BN=96) -> g_logits
    {
        dim3 grid(NWTS / 96, NA / 128);
        gemm_logits96<<<grid, 256>>>(inst, Ww, bw);
    }

    // 4) fused softmax + compacted aggregation (fp8 features)
    agg_kernel<<<NA, 256>>>();

    // 5) output GEMM: g_feats @ Wo + bo + inst -> d_out
    {
        dim3 grid(ED / 64, NA / 128);
        gemm_bf16_out<<<grid, 256>>>(Wo, bo, inst, out);
    }
}